// round 7
// baseline (speedup 1.0000x reference)
#include <cuda_runtime.h>
#include <stdint.h>

#define NXD   432
#define NYD   496
#define BD    4
#define CD    64
#define PLANE (NXD * NYD)        // 214272; PLANE/2 = 107136 = 558 * 192
#define NBINS 3
#define NPIL  64000
#define NBB   (NBINS * BD)

__device__ unsigned short g_idx[NBB * PLANE];   // 5.1 MB, 0xFFFF = empty

__global__ void init_idx_kernel() {
    const int n8 = (NBB * PLANE) / 8;   // 321408
    int t = blockIdx.x * blockDim.x + threadIdx.x;
    if (t < n8) reinterpret_cast<int4*>(g_idx)[t] = make_int4(-1, -1, -1, -1);
}

__global__ void scatter_idx_kernel(const int* __restrict__ c0,
                                   const int* __restrict__ c1,
                                   const int* __restrict__ c2) {
    int t = blockIdx.x * blockDim.x + threadIdx.x;
    if (t >= NBINS * NPIL) return;
    int bin = t / NPIL;
    int p   = t - bin * NPIL;
    const int* cbase = (bin == 0) ? c0 : (bin == 1) ? c1 : c2;
    int4 cr = reinterpret_cast<const int4*>(cbase)[p];   // [b, z, y, x]
    int local = cr.y + cr.z * NXD + cr.w;
    g_idx[(bin * BD + cr.x) * PLANE + local] = (unsigned short)p;
}

// Branch-free gather: one thread per TWO consecutive BEV positions, 64 channels.
__global__ void __launch_bounds__(192)
gather_kernel(const float* __restrict__ p0,
              const float* __restrict__ p1,
              const float* __restrict__ p2,
              float* __restrict__ out) {
    int t   = blockIdx.x * 192 + threadIdx.x;   // 0 .. PLANE/2-1, exact cover
    int pos = t * 2;
    int bb  = blockIdx.y;
    int bin = bb >> 2;
    const float* pil = (bin == 0) ? p0 : (bin == 1) ? p1 : p2;

    unsigned int packed =
        *reinterpret_cast<const unsigned int*>(g_idx + (size_t)bb * PLANE + pos);
    unsigned int i0 = packed & 0xFFFFu;
    unsigned int i1 = packed >> 16;
    bool o0 = i0 != 0xFFFFu;
    bool o1 = i1 != 0xFFFFu;

    const float4* r0p =
        reinterpret_cast<const float4*>(pil) + (size_t)(o0 ? i0 : 0u) * (CD / 4);
    const float4* r1p =
        reinterpret_cast<const float4*>(pil) + (size_t)(o1 ? i1 : 0u) * (CD / 4);
    float* o = out + (size_t)bb * CD * PLANE + pos;

#pragma unroll
    for (int ch = 0; ch < 4; ch++) {            // 4 chunks of 16 channels
        float4 a[4], b[4];
#pragma unroll
        for (int q = 0; q < 4; q++) {
            a[q] = __ldg(r0p + ch * 4 + q);
            b[q] = __ldg(r1p + ch * 4 + q);
        }
#pragma unroll
        for (int q = 0; q < 4; q++) {
            int c = ch * 16 + q * 4;
            float2 v;
            v.x = o0 ? a[q].x : 0.f;  v.y = o1 ? b[q].x : 0.f;
            __stcs(reinterpret_cast<float2*>(o + (size_t)(c + 0) * PLANE), v);
            v.x = o0 ? a[q].y : 0.f;  v.y = o1 ? b[q].y : 0.f;
            __stcs(reinterpret_cast<float2*>(o + (size_t)(c + 1) * PLANE), v);
            v.x = o0 ? a[q].z : 0.f;  v.y = o1 ? b[q].z : 0.f;
            __stcs(reinterpret_cast<float2*>(o + (size_t)(c + 2) * PLANE), v);
            v.x = o0 ? a[q].w : 0.f;  v.y = o1 ? b[q].w : 0.f;
            __stcs(reinterpret_cast<float2*>(o + (size_t)(c + 3) * PLANE), v);
        }
    }
}

extern "C" void kernel_launch(void* const* d_in, const int* in_sizes, int n_in,
                              void* d_out, int out_size) {
    const float* pf0 = (const float*)d_in[0];
    const int*   vc0 = (const int*)  d_in[1];
    const float* pf1 = (const float*)d_in[2];
    const int*   vc1 = (const int*)  d_in[3];
    const float* pf2 = (const float*)d_in[4];
    const int*   vc2 = (const int*)  d_in[5];
    float* out = (float*)d_out;

    {
        int n8 = (NBB * PLANE) / 8;
        init_idx_kernel<<<(n8 + 255) / 256, 256>>>();
    }
    {
        int n = NBINS * NPIL;
        scatter_idx_kernel<<<(n + 255) / 256, 256>>>(vc0, vc1, vc2);
    }
    {
        dim3 blk((PLANE / 2) / 192, NBB);   // (558, 12), exact cover
        gather_kernel<<<blk, 192>>>(pf0, pf1, pf2, out);
    }
}

// round 8
// speedup vs baseline: 1.2003x; 1.2003x over previous
#include <cuda_runtime.h>
#include <stdint.h>

// Problem constants (fixed by the reference)
#define NXD   432
#define NYD   496
#define BD    4
#define CD    64
#define PLANE (NXD * NYD)        // 214272 = 837 * 256 (exact)
#define NBINS 3
#define NPIL  64000              // < 65535 -> fits uint16
#define NBB   (NBINS * BD)       // 12 (bin,b) canvases

// Scratch: pillar-index canvas, 0xFFFF = empty. 12 * 214272 * 2B ~= 5.1 MB.
__device__ unsigned short g_idx[NBB * PLANE];

// ---------------------------------------------------------------------------
// Kernel 1: fill index canvas with 0xFFFF (int4 = 8 u16 per store)
// ---------------------------------------------------------------------------
__global__ void init_idx_kernel() {
    const int n8 = (NBB * PLANE) / 8;   // 321408
    int t = blockIdx.x * blockDim.x + threadIdx.x;
    if (t < n8) {
        reinterpret_cast<int4*>(g_idx)[t] = make_int4(-1, -1, -1, -1);
    }
}

// ---------------------------------------------------------------------------
// Kernel 2: scatter pillar indices into the canvas.
// coords row layout: [b, z, y, x]; local = z + y*NX + x  (nz == 1)
// ---------------------------------------------------------------------------
__global__ void scatter_idx_kernel(const int* __restrict__ c0,
                                   const int* __restrict__ c1,
                                   const int* __restrict__ c2) {
    int t = blockIdx.x * blockDim.x + threadIdx.x;
    if (t >= NBINS * NPIL) return;
    int bin = t / NPIL;
    int p   = t - bin * NPIL;
    const int* cbase = (bin == 0) ? c0 : (bin == 1) ? c1 : c2;
    int4 cr = reinterpret_cast<const int4*>(cbase)[p];   // [b, z, y, x]
    int local = cr.y + cr.z * NXD + cr.w;
    g_idx[(bin * BD + cr.x) * PLANE + local] = (unsigned short)p;
}

// ---------------------------------------------------------------------------
// Kernel 3: branch-free gather — EXACT R5 structure (the 121.6us winner),
// only the index load is now u16.
// One thread per BEV position, all 64 channels:
//  - index load: coalesced u16 (64B per warp)
//  - pillar row: 16 x LDG.128 via clamped pointer (occupied rows read once
//    chip-wide; empty lanes broadcast row 0 -> L1 hit)
//  - stores: 64 unconditional warp-coalesced plain STG.32 (128B/warp/instr)
// ---------------------------------------------------------------------------
__global__ void __launch_bounds__(256)
gather_kernel(const float* __restrict__ p0,
              const float* __restrict__ p1,
              const float* __restrict__ p2,
              float* __restrict__ out) {
    int pos = blockIdx.x * 256 + threadIdx.x;  // 0..PLANE-1 (exact cover)
    int bb  = blockIdx.y;                      // 0..11 = bin*4 + b
    int bin = bb >> 2;
    const float* pil = (bin == 0) ? p0 : (bin == 1) ? p1 : p2;

    unsigned int idx = __ldg(g_idx + (size_t)bb * PLANE + pos);
    bool occ = idx != 0xFFFFu;
    const float4* row =
        reinterpret_cast<const float4*>(pil) + (size_t)(occ ? idx : 0u) * (CD / 4);
    float* o = out + (size_t)bb * CD * PLANE + pos;

#pragma unroll
    for (int ch = 0; ch < 4; ch++) {           // 4 chunks of 16 channels
        float4 r[4];
#pragma unroll
        for (int q = 0; q < 4; q++) r[q] = __ldg(row + ch * 4 + q);
#pragma unroll
        for (int q = 0; q < 4; q++) {
            int c = ch * 16 + q * 4;
            o[(size_t)(c + 0) * PLANE] = occ ? r[q].x : 0.f;
            o[(size_t)(c + 1) * PLANE] = occ ? r[q].y : 0.f;
            o[(size_t)(c + 2) * PLANE] = occ ? r[q].z : 0.f;
            o[(size_t)(c + 3) * PLANE] = occ ? r[q].w : 0.f;
        }
    }
}

// ---------------------------------------------------------------------------
// Launch. Input order (metadata): pf0, vc0, pf1, vc1, pf2, vc2.
// Output: 3 canvases [4,64,496,432] f32 concatenated.
// ---------------------------------------------------------------------------
extern "C" void kernel_launch(void* const* d_in, const int* in_sizes, int n_in,
                              void* d_out, int out_size) {
    const float* pf0 = (const float*)d_in[0];
    const int*   vc0 = (const int*)  d_in[1];
    const float* pf1 = (const float*)d_in[2];
    const int*   vc1 = (const int*)  d_in[3];
    const float* pf2 = (const float*)d_in[4];
    const int*   vc2 = (const int*)  d_in[5];
    float* out = (float*)d_out;

    // 1) reset index canvas (5.1 MB of 0xFFFF)
    {
        int n8 = (NBB * PLANE) / 8;
        init_idx_kernel<<<(n8 + 255) / 256, 256>>>();
    }
    // 2) scatter pillar indices (tiny)
    {
        int n = NBINS * NPIL;
        scatter_idx_kernel<<<(n + 255) / 256, 256>>>(vc0, vc1, vc2);
    }
    // 3) branch-free gather -> dense output (streaming-store bound)
    {
        dim3 blocks(PLANE / 256, NBB);   // (837, 12), exact cover
        gather_kernel<<<blocks, 256>>>(pf0, pf1, pf2, out);
    }
}